// round 6
// baseline (speedup 1.0000x reference)
#include <cuda_runtime.h>
#include <math.h>

// loss = sum_c logdet(G_c + 0.5 I_128) - logdet(G + 0.5 I_128) + 1920*ln2
// where G_c = F_c^T F_c (per-class 128x128 Gram), G = sum_c G_c.
// Derivation: det(sI_m + F F^T) = s^(m-k) det(sI_k + F^T F) for any m,k.

#define MF 1536
#define KD 128
#define NC 16

__device__ float g_gram[NC][KD][KD];
__device__ float g_ld[NC + 1];

// ---------------------------------------------------------------------------
// Kernel 1: per-class Gram matrices. One block per class, 256 threads laid out
// as 16x16; each thread register-accumulates an 8x8 tile of the 128x128 output.
// ---------------------------------------------------------------------------
__global__ __launch_bounds__(256) void gram_kernel(const float* __restrict__ feats,
                                                   const int* __restrict__ labels) {
    const int c   = blockIdx.x;
    const int tid = threadIdx.x;
    const int ty  = tid >> 4;   // 0..15 -> output rows ty*8..ty*8+7
    const int tx  = tid & 15;   // 0..15 -> output cols tx*8..tx*8+7

    __shared__ int   s_idx[MF];
    __shared__ int   s_cnt;
    __shared__ float s_rows[8][KD];

    if (tid == 0) s_cnt = 0;
    __syncthreads();
    for (int m = tid; m < MF; m += 256) {
        if (labels[m] == c) {
            int p = atomicAdd(&s_cnt, 1);
            s_idx[p] = m;
        }
    }
    __syncthreads();
    const int cnt = s_cnt;

    float acc[8][8];
#pragma unroll
    for (int a = 0; a < 8; a++)
#pragma unroll
        for (int b = 0; b < 8; b++) acc[a][b] = 0.f;

    for (int base = 0; base < cnt; base += 8) {
        const int nb = min(8, cnt - base);
        __syncthreads();   // s_rows reuse guard
        for (int t = tid; t < nb * KD; t += 256) {
            int r = t >> 7, col = t & 127;
            s_rows[r][col] = feats[s_idx[base + r] * KD + col];
        }
        __syncthreads();
        for (int r = 0; r < nb; r++) {
            float fa[8], fb[8];
#pragma unroll
            for (int a = 0; a < 8; a++) fa[a] = s_rows[r][ty * 8 + a];
#pragma unroll
            for (int b = 0; b < 8; b++) fb[b] = s_rows[r][tx * 8 + b];
#pragma unroll
            for (int a = 0; a < 8; a++)
#pragma unroll
                for (int b = 0; b < 8; b++)
                    acc[a][b] = fmaf(fa[a], fb[b], acc[a][b]);
        }
    }
#pragma unroll
    for (int a = 0; a < 8; a++)
#pragma unroll
        for (int b = 0; b < 8; b++)
            g_gram[c][ty * 8 + a][tx * 8 + b] = acc[a][b];
}

// ---------------------------------------------------------------------------
// Kernel 2: Cholesky logdet of 17 SPD 128x128 matrices (blocks 0..15: class
// Grams + 0.5I; block 16: total Gram + 0.5I). Packed lower triangle in static
// shared (33 KB). 512 threads = 4 threads per matrix row.
// logdet = sum_k log(pivot_k), pivot_k = A[k][k] just before its sqrt step.
// ---------------------------------------------------------------------------
__global__ __launch_bounds__(512) void chol_kernel() {
    const int b   = blockIdx.x;
    const int tid = threadIdx.x;
    const int i   = tid & 127;   // matrix row owned by this thread
    const int h   = tid >> 7;    // 0..3 : j-stripe within the row

    __shared__ float s_tri[KD * (KD + 1) / 2];   // packed lower triangle
    __shared__ float s_col[KD];
    __shared__ float s_red[KD];
    __shared__ float s_inv;

    const int rowbase = (i * (i + 1)) >> 1;

    // Load lower triangle (+0.5 on diagonal). Block 16 sums all class Grams.
    if (b < NC) {
        for (int j = h; j <= i; j += 4)
            s_tri[rowbase + j] = g_gram[b][i][j] + (j == i ? 0.5f : 0.f);
    } else {
        for (int j = h; j <= i; j += 4) {
            float s = (j == i) ? 0.5f : 0.f;
#pragma unroll
            for (int c = 0; c < NC; c++) s += g_gram[c][i][j];
            s_tri[rowbase + j] = s;
        }
    }

    float myld = 0.f;
    __syncthreads();

    for (int k = 0; k < KD; k++) {
        if (tid == k) {                       // h==0, i==k
            float p = s_tri[rowbase + k];     // pivot (fully updated)
            myld  = logf(p);
            s_inv = rsqrtf(p);
        }
        __syncthreads();
        if (h == 0 && i > k)
            s_col[i] = s_tri[rowbase + k] * s_inv;   // L(i,k)
        __syncthreads();
        if (i > k) {
            const float aik = s_col[i];
            for (int j = k + 1 + h; j <= i; j += 4)
                s_tri[rowbase + j] -= aik * s_col[j];
        }
        __syncthreads();
    }

    if (h == 0) s_red[i] = myld;   // exactly one pivot log per row-thread
    __syncthreads();
    if (tid == 0) {
        float s = 0.f;
        for (int j = 0; j < KD; j++) s += s_red[j];
        g_ld[b] = s;
    }
}

// ---------------------------------------------------------------------------
// Kernel 3: final scalar.
// ---------------------------------------------------------------------------
__global__ void finalize_kernel(float* __restrict__ out) {
    float s = 0.f;
#pragma unroll
    for (int c = 0; c < NC; c++) s += g_ld[c];
    s -= g_ld[NC];
    out[0] = s + 1920.0f * 0.69314718055994530942f;   // +1920*ln2
}

extern "C" void kernel_launch(void* const* d_in, const int* in_sizes, int n_in,
                              void* d_out, int out_size) {
    const float* feats  = (const float*)d_in[0];
    const int*   labels = (const int*)d_in[1];
    // d_in[2] = ious: unused (reference uses coef = ones_like(ious))

    gram_kernel<<<NC, 256>>>(feats, labels);
    chol_kernel<<<NC + 1, 512>>>();
    finalize_kernel<<<1, 1>>>((float*)d_out);
}